// round 1
// baseline (speedup 1.0000x reference)
#include <cuda_runtime.h>
#include <cstdint>
#include <math.h>

#define H 2048
#define E 64
#define BM 128
#define BK 32
#define XSTR 130   // padded row stride for x smem tile (even, keeps float2 alignment)

__device__ float g_scores[16384 * E];   // 4 MB scratch (static: no allocation allowed)
__device__ float g_bias[E];
__device__ float g_cnt[E];
__device__ float g_psum[E];

typedef unsigned long long ull;

__device__ __forceinline__ ull pack2(float v) {
    ull r; asm("mov.b64 %0, {%1, %1};" : "=l"(r) : "f"(v)); return r;
}
__device__ __forceinline__ void fma2(ull& d, ull a, ull b) {
    asm("fma.rn.f32x2 %0, %1, %2, %0;" : "+l"(d) : "l"(a), "l"(b));
}

// ---------------------------------------------------------------------------
// Pass 0: per-expert bias + zero accumulators
// ---------------------------------------------------------------------------
__global__ __launch_bounds__(64) void init_kernel(const float* __restrict__ rep,
                                                  const float* __restrict__ loads,
                                                  const float* __restrict__ counts,
                                                  const int* __restrict__ total) {
    int t = threadIdx.x;
    float lt = logf((float)(*total) + 1.0f);
    float expl = 0.1f * sqrtf(lt / (counts[t] + 1e-10f));
    float ul = 0.9f * loads[t] + 0.1f * loads[t];   // mirror reference EMA exactly
    g_bias[t] = 0.1f * rep[t] - 0.1f * ul + expl;
    g_cnt[t] = 0.0f;
    g_psum[t] = 0.0f;
}

// ---------------------------------------------------------------------------
// Pass 1: fp32 GEMM  scores[T,64] = X[T,2048] @ W[64,2048]^T
// 128x64 block tile, BK=32, register prefetch, packed f32x2 FMA
// (accumulators hold a pair of adjacent tokens -> A loads are LDS.64, no packs)
// ---------------------------------------------------------------------------
__global__ __launch_bounds__(256) void gemm_kernel(const float* __restrict__ X,
                                                   const float* __restrict__ W) {
    __shared__ float xs[BK][XSTR];   // transposed: xs[k][token]
    __shared__ float ws[BK][E];      // transposed: ws[k][expert]

    int t = threadIdx.x;
    int tokBase = blockIdx.x * BM;
    int tx = t & 15;        // expert group (4 experts)
    int ty = t >> 4;        // token group  (8 tokens = 4 pairs)

    // global-load assignments
    int ltok  = t >> 1;           // 0..127
    int lslot = (t & 1) * 4;      // float4 slot base within 32-float row chunk
    const float4* Xv = (const float4*)(X + (size_t)(tokBase + ltok) * H);
    int we    = t >> 2;           // 0..63
    int wslot = (t & 3) * 2;
    const float4* Wv = (const float4*)(W + (size_t)we * H);

    float4 xr[4], wr[2];
#pragma unroll
    for (int j = 0; j < 4; ++j) xr[j] = Xv[lslot + j];
#pragma unroll
    for (int j = 0; j < 2; ++j) wr[j] = Wv[wslot + j];

    ull acc[4][4];
#pragma unroll
    for (int p = 0; p < 4; ++p)
#pragma unroll
        for (int e = 0; e < 4; ++e) acc[p][e] = 0ull;

    const int NC = H / BK;   // 64 k-chunks
    for (int kc = 0; kc < NC; ++kc) {
        // stage regs -> smem (transposed)
#pragma unroll
        for (int j = 0; j < 4; ++j) {
            int kk = (lslot + j) * 4;
            xs[kk + 0][ltok] = xr[j].x;
            xs[kk + 1][ltok] = xr[j].y;
            xs[kk + 2][ltok] = xr[j].z;
            xs[kk + 3][ltok] = xr[j].w;
        }
#pragma unroll
        for (int j = 0; j < 2; ++j) {
            int kk = (wslot + j) * 4;
            ws[kk + 0][we] = wr[j].x;
            ws[kk + 1][we] = wr[j].y;
            ws[kk + 2][we] = wr[j].z;
            ws[kk + 3][we] = wr[j].w;
        }
        __syncthreads();

        // prefetch next chunk into registers (hides HBM latency under compute)
        if (kc + 1 < NC) {
#pragma unroll
            for (int j = 0; j < 4; ++j) xr[j] = Xv[(kc + 1) * 8 + lslot + j];
#pragma unroll
            for (int j = 0; j < 2; ++j) wr[j] = Wv[(kc + 1) * 8 + wslot + j];
        }

#pragma unroll
        for (int k = 0; k < BK; ++k) {
            ull av[4];
#pragma unroll
            for (int p = 0; p < 4; ++p)
                av[p] = *(const ull*)&xs[k][ty * 8 + 2 * p];   // LDS.64 token pair
            float4 bv = *(const float4*)&ws[k][tx * 4];        // LDS.128
            ull bd[4] = {pack2(bv.x), pack2(bv.y), pack2(bv.z), pack2(bv.w)};
#pragma unroll
            for (int e = 0; e < 4; ++e)
#pragma unroll
                for (int p = 0; p < 4; ++p)
                    fma2(acc[p][e], av[p], bd[e]);
        }
        __syncthreads();
    }

    // epilogue: write scores [token][expert]
#pragma unroll
    for (int p = 0; p < 4; ++p) {
        int tok = tokBase + ty * 8 + 2 * p;
#pragma unroll
        for (int e = 0; e < 4; ++e) {
            float2 v = *(float2*)&acc[p][e];
            int ex = tx * 4 + e;
            g_scores[(size_t)tok * E + ex] = v.x;
            g_scores[(size_t)(tok + 1) * E + ex] = v.y;
        }
    }
}

// ---------------------------------------------------------------------------
// Pass 2: per-token bias add, top-2 (tie -> lower index), softmax(2) weights,
// full softmax accumulation for aux loss. One warp per token.
// ---------------------------------------------------------------------------
__global__ __launch_bounds__(256) void topk_kernel(float* __restrict__ out, int T) {
    __shared__ float sP[E];
    __shared__ float sC[E];
    int t = threadIdx.x;
    int l = t & 31, w = t >> 5;
    if (t < E) { sP[t] = 0.0f; sC[t] = 0.0f; }
    __syncthreads();

    float bx = g_bias[2 * l], by = g_bias[2 * l + 1];
    float accx = 0.0f, accy = 0.0f;
    int tokBase = blockIdx.x * 128;

    for (int i = 0; i < 16; ++i) {
        int tok = tokBase + i * 8 + w;
        float2 s = *(const float2*)&g_scores[(size_t)tok * E + 2 * l];
        s.x += bx;
        s.y += by;

        // per-lane sorted pair (value desc, tie -> lower index)
        float av, bv; int ai, bi;
        if (s.x >= s.y) { av = s.x; ai = 2 * l;     bv = s.y; bi = 2 * l + 1; }
        else            { av = s.y; ai = 2 * l + 1; bv = s.x; bi = 2 * l; }

#pragma unroll
        for (int off = 16; off > 0; off >>= 1) {
            float oav = __shfl_xor_sync(0xffffffffu, av, off);
            int   oai = __shfl_xor_sync(0xffffffffu, ai, off);
            float obv = __shfl_xor_sync(0xffffffffu, bv, off);
            int   obi = __shfl_xor_sync(0xffffffffu, bi, off);
            if (oav > av || (oav == av && oai < ai)) {
                bool mine2 = (av > obv) || (av == obv && ai < obi);
                bv = mine2 ? av : obv;
                bi = mine2 ? ai : obi;
                av = oav; ai = oai;
            } else {
                if (oav > bv || (oav == bv && oai < bi)) { bv = oav; bi = oai; }
            }
        }

        // full softmax over 64 experts (max = top-1 value)
        float e0 = __expf(s.x - av);
        float e1 = __expf(s.y - av);
        float sum = e0 + e1;
#pragma unroll
        for (int off = 16; off > 0; off >>= 1)
            sum += __shfl_xor_sync(0xffffffffu, sum, off);
        float r = 1.0f / sum;
        accx += e0 * r;
        accy += e1 * r;

        if (l == 0) {
            float tt = __expf(bv - av);          // exp(s2 - s1), s1 >= s2
            float w1 = 1.0f / (1.0f + tt);
            out[2 * tok]     = w1;
            out[2 * tok + 1] = tt * w1;
            out[2 * T + 2 * tok]     = (float)ai;
            out[2 * T + 2 * tok + 1] = (float)bi;
            atomicAdd(&sC[ai], 1.0f);
            atomicAdd(&sC[bi], 1.0f);
        }
    }

    atomicAdd(&sP[2 * l],     accx);
    atomicAdd(&sP[2 * l + 1], accy);
    __syncthreads();
    if (t < E) {
        atomicAdd(&g_psum[t], sP[t]);
        atomicAdd(&g_cnt[t],  sC[t]);
    }
}

// ---------------------------------------------------------------------------
// Pass 3: aux loss = E * sum_e (cnt/T) * (psum/T)
// ---------------------------------------------------------------------------
__global__ __launch_bounds__(64) void aux_kernel(float* __restrict__ out, int T) {
    __shared__ float red[64];
    int t = threadIdx.x;
    red[t] = g_cnt[t] * g_psum[t];
    __syncthreads();
    if (t < 32) {
        float v = red[t] + red[t + 32];
#pragma unroll
        for (int off = 16; off > 0; off >>= 1)
            v += __shfl_xor_sync(0xffffffffu, v, off);
        if (t == 0) {
            float invT = 1.0f / (float)T;
            out[4 * T] = v * 64.0f * invT * invT;
        }
    }
}

// ---------------------------------------------------------------------------
extern "C" void kernel_launch(void* const* d_in, const int* in_sizes, int n_in,
                              void* d_out, int out_size) {
    const float* x      = (const float*)d_in[0];
    const float* gw     = (const float*)d_in[1];
    const float* rep    = (const float*)d_in[2];
    const float* loads  = (const float*)d_in[3];
    const float* counts = (const float*)d_in[4];
    const int*   total  = (const int*)d_in[5];
    float* out = (float*)d_out;

    int T = in_sizes[0] / H;   // 16384

    init_kernel<<<1, 64>>>(rep, loads, counts, total);
    gemm_kernel<<<T / BM, 256>>>(x, gw);
    topk_kernel<<<T / 128, 256>>>(out, T);
    aux_kernel<<<1, 64>>>(out, T);
}

// round 3
// speedup vs baseline: 1.3386x; 1.3386x over previous
#include <cuda_runtime.h>
#include <cstdint>
#include <math.h>

#define H 2048
#define E 64
#define BM 128
#define NKK (H / 16)   // 128 k16 steps

// ---------------- device globals (no allocation allowed) -------------------
__device__ float g_bias[E];
__device__ float g_cnt[E];
__device__ float g_psum[E];
// W planes prepacked in mma B-fragment per-lane order:
// index = (kk*8 + gtile)*32 + lane
__device__ uint4 g_wp16[NKK * 8 * 32];   // {h_b0, h_b1, m_b0, m_b1}
__device__ uint2 g_wp8 [NKK * 8 * 32];   // {l_b0, l_b1}

// ---------------- helpers ---------------------------------------------------
// cvt two f32 -> packed bf16x2 (f0 -> low half)
#define CVT2(out, f0, f1) \
    asm("cvt.rn.bf16x2.f32 %0, %1, %2;" : "=r"(out) : "f"(f1), "f"(f0))

// split (f0,f1) into 3 bf16 planes (packed pairs): exact residual decomposition
__device__ __forceinline__ void split2(float f0, float f1,
                                       uint32_t& u, uint32_t& v, uint32_t& w) {
    CVT2(u, f0, f1);
    float h0 = __uint_as_float(u << 16);
    float h1 = __uint_as_float(u & 0xffff0000u);
    float r0 = f0 - h0, r1 = f1 - h1;
    CVT2(v, r0, r1);
    float m0 = __uint_as_float(v << 16);
    float m1 = __uint_as_float(v & 0xffff0000u);
    CVT2(w, r0 - m0, r1 - m1);
}

__device__ __forceinline__ void mma16816(float* c,
                                         uint32_t a0, uint32_t a1, uint32_t a2, uint32_t a3,
                                         uint32_t b0, uint32_t b1) {
    asm("mma.sync.aligned.m16n8k16.row.col.f32.bf16.bf16.f32 "
        "{%0,%1,%2,%3}, {%4,%5,%6,%7}, {%8,%9}, {%0,%1,%2,%3};"
        : "+f"(c[0]), "+f"(c[1]), "+f"(c[2]), "+f"(c[3])
        : "r"(a0), "r"(a1), "r"(a2), "r"(a3), "r"(b0), "r"(b1));
}

// ---------------------------------------------------------------------------
__global__ __launch_bounds__(64) void init_kernel(const float* __restrict__ rep,
                                                  const float* __restrict__ loads,
                                                  const float* __restrict__ counts,
                                                  const int* __restrict__ total) {
    int t = threadIdx.x;
    float lt = logf((float)(*total) + 1.0f);
    float expl = 0.1f * sqrtf(lt / (counts[t] + 1e-10f));
    float ul = 0.9f * loads[t] + 0.1f * loads[t];   // mirror reference EMA exactly
    g_bias[t] = 0.1f * rep[t] - 0.1f * ul + expl;
    g_cnt[t] = 0.0f;
    g_psum[t] = 0.0f;
}

// W -> 3 bf16 planes, packed directly in B-fragment per-lane order.
// B frag (m16n8k16): b0 = W[n][k16 + 2q, +1], b1 = W[n][k16 + 8 + 2q, +1]
//   where n = gtile*8 + lane/4, q = lane%4.
__global__ __launch_bounds__(256) void wprep_kernel(const float* __restrict__ W) {
    int id = blockIdx.x * 256 + threadIdx.x;   // 0..32767
    int lane = id & 31;
    int gt = (id >> 5) & 7;
    int kk = id >> 8;
    int n = gt * 8 + (lane >> 2);
    int q = lane & 3;
    int p0 = n * (H / 2) + kk * 8 + q;   // pair index into W
    int p1 = p0 + 4;
    float2 f0 = ((const float2*)W)[p0];
    float2 f1 = ((const float2*)W)[p1];
    uint32_t h0, m0, l0, h1, m1, l1;
    split2(f0.x, f0.y, h0, m0, l0);
    split2(f1.x, f1.y, h1, m1, l1);
    g_wp16[id] = make_uint4(h0, h1, m0, m1);
    g_wp8[id]  = make_uint2(l0, l1);
}

// ---------------------------------------------------------------------------
// Fused: 3-plane bf16 mma.sync GEMM + top-2/softmax/aux epilogue.
// 8 warps: warp = (mg = wid&3) token group of 32, (ng = wid>>2) expert half of 32.
// ---------------------------------------------------------------------------
__global__ __launch_bounds__(256, 1) void gemm_kernel(const float* __restrict__ X,
                                                      float* __restrict__ out, int T) {
    __shared__ float sS[128][66];
    __shared__ float sB[E], sP[E], sC[E];

    int tid = threadIdx.x, lane = tid & 31, wid = tid >> 5;
    int mg = wid & 3, ng = wid >> 2;
    int q = lane & 3;
    if (tid < E) { sB[tid] = g_bias[tid]; sP[tid] = 0.0f; sC[tid] = 0.0f; }

    int tokBase = blockIdx.x * BM;

    // A row pointers: rows mg*32 + lane/4 + {0,8,16,24}, col base 2q
    const float* xp[4];
    int r0 = tokBase + mg * 32 + (lane >> 2);
#pragma unroll
    for (int i = 0; i < 4; ++i)
        xp[i] = X + (size_t)(r0 + i * 8) * H + 2 * q;

    // B fragment pointers
    const uint4* bp16 = g_wp16 + (size_t)(ng * 4) * 32 + lane;
    const uint2* bp8  = g_wp8  + (size_t)(ng * 4) * 32 + lane;

    float acc[2][4][4];
#pragma unroll
    for (int s = 0; s < 2; ++s)
#pragma unroll
        for (int t = 0; t < 4; ++t)
#pragma unroll
            for (int c = 0; c < 4; ++c) acc[s][t][c] = 0.0f;

    // prefetch kk = 0
    float2 a_nxt[8];
    uint4  b16n[4];
    uint2  b8n[4];
#pragma unroll
    for (int i = 0; i < 4; ++i) {
        a_nxt[i * 2]     = *(const float2*)(xp[i]);
        a_nxt[i * 2 + 1] = *(const float2*)(xp[i] + 8);
    }
#pragma unroll
    for (int t = 0; t < 4; ++t) { b16n[t] = bp16[t * 32]; b8n[t] = bp8[t * 32]; }

    for (int kk = 0; kk < NKK; ++kk) {
        float2 a[8];
        uint4 b16[4];
        uint2 b8[4];
#pragma unroll
        for (int j = 0; j < 8; ++j) a[j] = a_nxt[j];
#pragma unroll
        for (int t = 0; t < 4; ++t) { b16[t] = b16n[t]; b8[t] = b8n[t]; }

        if (kk + 1 < NKK) {
#pragma unroll
            for (int i = 0; i < 4; ++i) {
                a_nxt[i * 2]     = *(const float2*)(xp[i] + (kk + 1) * 16);
                a_nxt[i * 2 + 1] = *(const float2*)(xp[i] + (kk + 1) * 16 + 8);
            }
            const uint4* p16 = bp16 + (size_t)(kk + 1) * 256;
            const uint2* p8  = bp8  + (size_t)(kk + 1) * 256;
#pragma unroll
            for (int t = 0; t < 4; ++t) { b16n[t] = p16[t * 32]; b8n[t] = p8[t * 32]; }
        }

        // split A into 3 planes (per-lane registers)
        uint32_t ah[8], am[8], al[8];
#pragma unroll
        for (int j = 0; j < 8; ++j) split2(a[j].x, a[j].y, ah[j], am[j], al[j]);

#pragma unroll
        for (int t = 0; t < 4; ++t) {
            uint32_t bh0 = b16[t].x, bh1 = b16[t].y;
            uint32_t bm0 = b16[t].z, bm1 = b16[t].w;
            uint32_t bl0 = b8[t].x,  bl1 = b8[t].y;
#pragma unroll
            for (int s = 0; s < 2; ++s) {
                int j0 = s * 4;
                // frag order: a0=(r,lo) a1=(r+8,lo) a2=(r,hi) a3=(r+8,hi)
                uint32_t H0 = ah[j0], H1 = ah[j0 + 2], H2 = ah[j0 + 1], H3 = ah[j0 + 3];
                uint32_t M0 = am[j0], M1 = am[j0 + 2], M2 = am[j0 + 1], M3 = am[j0 + 3];
                uint32_t L0 = al[j0], L1 = al[j0 + 2], L2 = al[j0 + 1], L3 = al[j0 + 3];
                mma16816(acc[s][t], H0, H1, H2, H3, bh0, bh1);
                mma16816(acc[s][t], H0, H1, H2, H3, bm0, bm1);
                mma16816(acc[s][t], M0, M1, M2, M3, bh0, bh1);
                mma16816(acc[s][t], H0, H1, H2, H3, bl0, bl1);
                mma16816(acc[s][t], M0, M1, M2, M3, bm0, bm1);
                mma16816(acc[s][t], L0, L1, L2, L3, bh0, bh1);
            }
        }
    }

    // ---- store score fragments to smem ----
#pragma unroll
    for (int s = 0; s < 2; ++s) {
        int rr = mg * 32 + s * 16 + (lane >> 2);
#pragma unroll
        for (int t = 0; t < 4; ++t) {
            int cc = ng * 32 + t * 8 + 2 * q;
            *(float2*)&sS[rr][cc]     = make_float2(acc[s][t][0], acc[s][t][1]);
            *(float2*)&sS[rr + 8][cc] = make_float2(acc[s][t][2], acc[s][t][3]);
        }
    }
    __syncthreads();

    // ---- per-token epilogue (threads 0..127, one token each) ----
    if (tid < 128) {
        float a = -1e30f, b = -1e30f;
        int ai = 0, bi = 0;
#pragma unroll
        for (int j = 0; j < 64; ++j) {
            float s = sS[tid][j] + sB[j];
            sS[tid][j] = s;
            if (s > a)      { b = a; bi = ai; a = s; ai = j; }
            else if (s > b) { b = s; bi = j; }
        }
        float sum = 0.0f;
#pragma unroll
        for (int j = 0; j < 64; ++j) {
            float e = __expf(sS[tid][j] - a);
            sS[tid][j] = e;
            sum += e;
        }
        float inv = 1.0f / sum;
#pragma unroll
        for (int j = 0; j < 64; ++j) sS[tid][j] *= inv;

        int tok = tokBase + tid;
        float tt = __expf(b - a);
        float w1 = 1.0f / (1.0f + tt);
        out[2 * tok]     = w1;
        out[2 * tok + 1] = tt * w1;
        out[2 * T + 2 * tok]     = (float)ai;
        out[2 * T + 2 * tok + 1] = (float)bi;
        atomicAdd(&sC[ai], 1.0f);
        atomicAdd(&sC[bi], 1.0f);
    }
    __syncthreads();

    // ---- per-expert prob column sums (all 256 threads) ----
    {
        int e = tid & 63, sl = tid >> 6;
        float s = 0.0f;
#pragma unroll
        for (int i = 0; i < 32; ++i)
            s += sS[sl * 32 + i][e];
        atomicAdd(&sP[e], s);
    }
    __syncthreads();
    if (tid < E) {
        atomicAdd(&g_psum[tid], sP[tid]);
        atomicAdd(&g_cnt[tid], sC[tid]);
    }
}

// ---------------------------------------------------------------------------
__global__ __launch_bounds__(64) void aux_kernel(float* __restrict__ out, int T) {
    __shared__ float red[64];
    int t = threadIdx.x;
    red[t] = g_cnt[t] * g_psum[t];
    __syncthreads();
    if (t < 32) {
        float v = red[t] + red[t + 32];
#pragma unroll
        for (int off = 16; off > 0; off >>= 1)
            v += __shfl_xor_sync(0xffffffffu, v, off);
        if (t == 0) {
            float invT = 1.0f / (float)T;
            out[4 * T] = v * 64.0f * invT * invT;
        }
    }
}

// ---------------------------------------------------------------------------
extern "C" void kernel_launch(void* const* d_in, const int* in_sizes, int n_in,
                              void* d_out, int out_size) {
    const float* x      = (const float*)d_in[0];
    const float* gw     = (const float*)d_in[1];
    const float* rep    = (const float*)d_in[2];
    const float* loads  = (const float*)d_in[3];
    const float* counts = (const float*)d_in[4];
    const int*   total  = (const int*)d_in[5];
    float* out = (float*)d_out;

    int T = in_sizes[0] / H;   // 16384

    init_kernel<<<1, 64>>>(rep, loads, counts, total);
    wprep_kernel<<<NKK * 8 * 32 / 256, 256>>>(gw);
    gemm_kernel<<<T / BM, 256>>>(x, out, T);
    aux_kernel<<<1, 64>>>(out, T);
}

// round 4
// speedup vs baseline: 1.6550x; 1.2363x over previous
#include <cuda_runtime.h>
#include <cuda_fp16.h>
#include <cstdint>
#include <math.h>

#define H 2048
#define E 64
#define BM 128
#define NKK (H / 16)   // 128 k16 steps
#define LSCALE 4096.0f
#define LINV   (1.0f / 4096.0f)

// ---------------- device globals (no allocation allowed) -------------------
__device__ float g_bias[E];
__device__ float g_cnt[E];
__device__ float g_psum[E];
__device__ unsigned g_done;
// W planes prepacked in mma B-fragment per-lane order:
// index = (kk*8 + gtile)*32 + lane ; {h_b0, h_b1, lScaled_b0, lScaled_b1}
__device__ uint4 g_wp[NKK * 8 * 32];

// ---------------- helpers ---------------------------------------------------
// split (f0,f1) -> fp16x2 hi plane + fp16x2 lo plane scaled by 2^12
__device__ __forceinline__ void splitH(float f0, float f1, uint32_t& h, uint32_t& l) {
    __half2 hh = __floats2half2_rn(f0, f1);
    float2 hf = __half22float2(hh);
    __half2 ll = __floats2half2_rn((f0 - hf.x) * LSCALE, (f1 - hf.y) * LSCALE);
    h = *(uint32_t*)&hh;
    l = *(uint32_t*)&ll;
}

__device__ __forceinline__ void mma16816(float* c,
                                         uint32_t a0, uint32_t a1, uint32_t a2, uint32_t a3,
                                         uint32_t b0, uint32_t b1) {
    asm("mma.sync.aligned.m16n8k16.row.col.f32.f16.f16.f32 "
        "{%0,%1,%2,%3}, {%4,%5,%6,%7}, {%8,%9}, {%0,%1,%2,%3};"
        : "+f"(c[0]), "+f"(c[1]), "+f"(c[2]), "+f"(c[3])
        : "r"(a0), "r"(a1), "r"(a2), "r"(a3), "r"(b0), "r"(b1));
}

// ---------------------------------------------------------------------------
// W prep (+ bias init + accumulator reset, folded into block 0)
// B frag (m16n8k16): b0 = W[n][k16 + 2q, +1], b1 = W[n][k16 + 8 + 2q, +1]
//   where n = gtile*8 + lane/4, q = lane%4.
__global__ __launch_bounds__(256) void wprep_kernel(const float* __restrict__ W,
                                                    const float* __restrict__ rep,
                                                    const float* __restrict__ loads,
                                                    const float* __restrict__ counts,
                                                    const int* __restrict__ total) {
    int id = blockIdx.x * 256 + threadIdx.x;   // 0..32767
    int lane = id & 31;
    int gt = (id >> 5) & 7;
    int kk = id >> 8;
    int n = gt * 8 + (lane >> 2);
    int q = lane & 3;
    int p0 = n * (H / 2) + kk * 8 + q;   // pair index into W
    int p1 = p0 + 4;
    float2 f0 = ((const float2*)W)[p0];
    float2 f1 = ((const float2*)W)[p1];
    uint32_t h0, l0, h1, l1;
    splitH(f0.x, f0.y, h0, l0);
    splitH(f1.x, f1.y, h1, l1);
    g_wp[id] = make_uint4(h0, h1, l0, l1);

    if (blockIdx.x == 0) {
        int t = threadIdx.x;
        if (t < E) {
            float lt = logf((float)(*total) + 1.0f);
            float expl = 0.1f * sqrtf(lt / (counts[t] + 1e-10f));
            float ul = 0.9f * loads[t] + 0.1f * loads[t];   // mirror reference EMA
            g_bias[t] = 0.1f * rep[t] - 0.1f * ul + expl;
            g_cnt[t] = 0.0f;
            g_psum[t] = 0.0f;
        }
        if (t == 64) g_done = 0u;
    }
}

// ---------------------------------------------------------------------------
// Fused: 2-plane fp16 mma.sync GEMM (3 terms, scaled lo-acc) + top-2/softmax/aux.
// 8 warps: (mg = wid&3) token group of 32, (ng = wid>>2) expert half of 32.
// ---------------------------------------------------------------------------
__global__ __launch_bounds__(256, 1) void gemm_kernel(const float* __restrict__ X,
                                                      float* __restrict__ out, int T) {
    __shared__ float sS[128][66];
    __shared__ float sB[E], sP[E], sC[E];
    __shared__ float sRed[64];
    __shared__ unsigned s_last;

    int tid = threadIdx.x, lane = tid & 31, wid = tid >> 5;
    int mg = wid & 3, ng = wid >> 2;
    int q = lane & 3;
    if (tid < E) { sB[tid] = g_bias[tid]; sP[tid] = 0.0f; sC[tid] = 0.0f; }

    int tokBase = blockIdx.x * BM;

    // A row pointers: rows mg*32 + lane/4 + {0,8,16,24}, col base 2q
    const float* xp[4];
    int r0 = tokBase + mg * 32 + (lane >> 2);
#pragma unroll
    for (int i = 0; i < 4; ++i)
        xp[i] = X + (size_t)(r0 + i * 8) * H + 2 * q;

    const uint4* bp = g_wp + (size_t)(ng * 4) * 32 + lane;

    float acc[2][4][4], accL[2][4][4];
#pragma unroll
    for (int s = 0; s < 2; ++s)
#pragma unroll
        for (int t = 0; t < 4; ++t)
#pragma unroll
            for (int c = 0; c < 4; ++c) { acc[s][t][c] = 0.0f; accL[s][t][c] = 0.0f; }

    // prefetch kk = 0
    float2 a_nxt[8];
    uint4  bn[4];
#pragma unroll
    for (int i = 0; i < 4; ++i) {
        a_nxt[i * 2]     = *(const float2*)(xp[i]);
        a_nxt[i * 2 + 1] = *(const float2*)(xp[i] + 8);
    }
#pragma unroll
    for (int t = 0; t < 4; ++t) bn[t] = bp[t * 32];

    for (int kk = 0; kk < NKK; ++kk) {
        float2 a[8];
        uint4 b[4];
#pragma unroll
        for (int j = 0; j < 8; ++j) a[j] = a_nxt[j];
#pragma unroll
        for (int t = 0; t < 4; ++t) b[t] = bn[t];

        if (kk + 1 < NKK) {
#pragma unroll
            for (int i = 0; i < 4; ++i) {
                a_nxt[i * 2]     = *(const float2*)(xp[i] + (kk + 1) * 16);
                a_nxt[i * 2 + 1] = *(const float2*)(xp[i] + (kk + 1) * 16 + 8);
            }
            const uint4* p = bp + (size_t)(kk + 1) * 256;
#pragma unroll
            for (int t = 0; t < 4; ++t) bn[t] = p[t * 32];
        }

        // split A into 2 fp16 planes (lo scaled by 2^12)
        uint32_t ah[8], al[8];
#pragma unroll
        for (int j = 0; j < 8; ++j) splitH(a[j].x, a[j].y, ah[j], al[j]);

#pragma unroll
        for (int t = 0; t < 4; ++t) {
            uint32_t bh0 = b[t].x, bh1 = b[t].y;
            uint32_t bl0 = b[t].z, bl1 = b[t].w;
#pragma unroll
            for (int s = 0; s < 2; ++s) {
                int j0 = s * 4;
                // frag order: a0=(r,lo) a1=(r+8,lo) a2=(r,hi) a3=(r+8,hi)
                uint32_t H0 = ah[j0], H1 = ah[j0 + 2], H2 = ah[j0 + 1], H3 = ah[j0 + 3];
                uint32_t L0 = al[j0], L1 = al[j0 + 2], L2 = al[j0 + 1], L3 = al[j0 + 3];
                mma16816(acc[s][t],  H0, H1, H2, H3, bh0, bh1);   // hh
                mma16816(accL[s][t], H0, H1, H2, H3, bl0, bl1);   // h * l*2^12
                mma16816(accL[s][t], L0, L1, L2, L3, bh0, bh1);   // l*2^12 * h
            }
        }
    }

    // ---- combine planes + store score fragments to smem ----
#pragma unroll
    for (int s = 0; s < 2; ++s) {
        int rr = mg * 32 + s * 16 + (lane >> 2);
#pragma unroll
        for (int t = 0; t < 4; ++t) {
            int cc = ng * 32 + t * 8 + 2 * q;
            *(float2*)&sS[rr][cc] = make_float2(
                acc[s][t][0] + accL[s][t][0] * LINV,
                acc[s][t][1] + accL[s][t][1] * LINV);
            *(float2*)&sS[rr + 8][cc] = make_float2(
                acc[s][t][2] + accL[s][t][2] * LINV,
                acc[s][t][3] + accL[s][t][3] * LINV);
        }
    }
    __syncthreads();

    // ---- per-token epilogue (threads 0..127, one token each) ----
    if (tid < 128) {
        float a = -1e30f, b = -1e30f;
        int ai = 0, bi = 0;
#pragma unroll
        for (int j = 0; j < 64; ++j) {
            float s = sS[tid][j] + sB[j];
            sS[tid][j] = s;
            if (s > a)      { b = a; bi = ai; a = s; ai = j; }
            else if (s > b) { b = s; bi = j; }
        }
        float sum = 0.0f;
#pragma unroll
        for (int j = 0; j < 64; ++j) {
            float e = __expf(sS[tid][j] - a);
            sS[tid][j] = e;
            sum += e;
        }
        float inv = 1.0f / sum;
#pragma unroll
        for (int j = 0; j < 64; ++j) sS[tid][j] *= inv;

        int tok = tokBase + tid;
        float tt = __expf(b - a);
        float w1 = 1.0f / (1.0f + tt);
        out[2 * tok]     = w1;
        out[2 * tok + 1] = tt * w1;
        out[2 * T + 2 * tok]     = (float)ai;
        out[2 * T + 2 * tok + 1] = (float)bi;
        atomicAdd(&sC[ai], 1.0f);
        atomicAdd(&sC[bi], 1.0f);
    }
    __syncthreads();

    // ---- per-expert prob column sums (all 256 threads) ----
    {
        int e = tid & 63, sl = tid >> 6;
        float s = 0.0f;
#pragma unroll
        for (int i = 0; i < 32; ++i)
            s += sS[sl * 32 + i][e];
        atomicAdd(&sP[e], s);
    }
    __syncthreads();
    if (tid < E) {
        atomicAdd(&g_psum[tid], sP[tid]);
        atomicAdd(&g_cnt[tid], sC[tid]);
    }

    // ---- last CTA computes aux loss ----
    if (tid == 0) {
        __threadfence();
        unsigned v = atomicAdd(&g_done, 1u);
        s_last = (v == gridDim.x - 1) ? 1u : 0u;
    }
    __syncthreads();
    if (s_last) {
        if (tid < 64) sRed[tid] = g_cnt[tid] * g_psum[tid];
    }
    __syncthreads();
    if (s_last && tid < 32) {
        float v = sRed[tid] + sRed[tid + 32];
#pragma unroll
        for (int off = 16; off > 0; off >>= 1)
            v += __shfl_xor_sync(0xffffffffu, v, off);
        if (tid == 0) {
            float invT = 1.0f / (float)T;
            out[4 * T] = v * 64.0f * invT * invT;
        }
    }
}

// ---------------------------------------------------------------------------
extern "C" void kernel_launch(void* const* d_in, const int* in_sizes, int n_in,
                              void* d_out, int out_size) {
    const float* x      = (const float*)d_in[0];
    const float* gw     = (const float*)d_in[1];
    const float* rep    = (const float*)d_in[2];
    const float* loads  = (const float*)d_in[3];
    const float* counts = (const float*)d_in[4];
    const int*   total  = (const int*)d_in[5];
    float* out = (float*)d_out;

    int T = in_sizes[0] / H;   // 16384

    wprep_kernel<<<NKK * 8 * 32 / 256, 256>>>(gw, rep, loads, counts, total);
    gemm_kernel<<<T / BM, 256>>>(x, out, T);
}